// round 8
// baseline (speedup 1.0000x reference)
#include <cuda_runtime.h>
#include <cuda_bf16.h>
#include <cstdint>

#define NQ    10
#define DIM   1024
#define NL    4
#define BATCH 4096
#define SEQ   512
#define PRED  96

// ---------------- device scratch (allocation-free) ----------------
__device__ float         g_h[BATCH * DIM];       // 16 MB intermediate h
__device__ __nv_bfloat16 g_xhi[BATCH * SEQ];
__device__ __nv_bfloat16 g_xlo[BATCH * SEQ];
__device__ __nv_bfloat16 g_whi[DIM * SEQ];
__device__ __nv_bfloat16 g_wlo[DIM * SEQ];
__device__ float2        g_gates[NL * NQ * 4];
__device__ int           g_perm[NL * DIM];

// ---------------- kernel 0: bf16 hi/lo split + gate/perm precompute ----------------
__global__ void split_kernel(const float* __restrict__ x, const float* __restrict__ w,
                             const float* __restrict__ qw) {
    int i = blockIdx.x * blockDim.x + threadIdx.x;
    if (i < BATCH * SEQ) {
        float v = x[i];
        __nv_bfloat16 h = __float2bfloat16(v);
        g_xhi[i] = h;
        g_xlo[i] = __float2bfloat16(v - __bfloat162float(h));
    }
    if (i < DIM * SEQ) {
        float v = w[i];
        __nv_bfloat16 h = __float2bfloat16(v);
        g_whi[i] = h;
        g_wlo[i] = __float2bfloat16(v - __bfloat162float(h));
    }
    if (blockIdx.x == 0) {
        int t = threadIdx.x;
        if (t < NL * NQ) {
            float phi   = qw[3 * t + 0];
            float theta = qw[3 * t + 1];
            float omega = qw[3 * t + 2];
            float s, c;
            sincosf(0.5f * theta, &s, &c);
            float a = 0.5f * (phi + omega);
            float b = 0.5f * (phi - omega);
            float sa, ca, sb, cb;
            sincosf(a, &sa, &ca);
            sincosf(b, &sb, &cb);
            g_gates[4 * t + 0] = make_float2( c * ca, -c * sa);
            g_gates[4 * t + 1] = make_float2(-s * cb, -s * sb);
            g_gates[4 * t + 2] = make_float2( s * cb, -s * sb);
            g_gates[4 * t + 3] = make_float2( c * ca,  c * sa);
        }
        for (int e = t; e < DIM; e += blockDim.x) {
            for (int l = 0; l < NL; l++) {
                int r = l % (NQ - 1) + 1;
                int p = e;
                for (int c = NQ - 1; c >= 0; c--) {
                    int bit = (p >> (NQ - 1 - c)) & 1;
                    int tgt = (c + r) % NQ;
                    p ^= bit << (NQ - 1 - tgt);
                }
                g_perm[l * DIM + e] = p;
            }
        }
    }
}

// ---------------- kernel 2: bf16 tensor-core GEMM (3-product, 4-stage) ----------------
#define GBM 128
#define GBN 128
#define GBK 16
#define SROW 24                 // bf16 per smem row (16 + 8 pad) = 48 bytes
#define MATB (GBM * SROW * 2)   // bytes per matrix tile = 6144
#define STAGEB (4 * MATB)       // bytes per stage = 24576
#define NSTAGE 4

#define MMA_BF16(C, A, B)                                                       \
    asm volatile("mma.sync.aligned.m16n8k16.row.col.f32.bf16.bf16.f32 "         \
                 "{%0,%1,%2,%3}, {%4,%5,%6,%7}, {%8,%9}, {%0,%1,%2,%3};"        \
                 : "+f"((C)[0]), "+f"((C)[1]), "+f"((C)[2]), "+f"((C)[3])       \
                 : "r"((A)[0]), "r"((A)[1]), "r"((A)[2]), "r"((A)[3]),          \
                   "r"((B)[0]), "r"((B)[1]))

#define LDM4(R, addr)                                                           \
    asm volatile("ldmatrix.sync.aligned.m8n8.x4.shared.b16 {%0,%1,%2,%3},[%4];" \
                 : "=r"((R)[0]), "=r"((R)[1]), "=r"((R)[2]), "=r"((R)[3])       \
                 : "r"(addr))

#define CPASYNC16(dst, src)                                                     \
    asm volatile("cp.async.cg.shared.global [%0], [%1], 16;" ::                 \
                 "r"(dst), "l"(src))

__global__ __launch_bounds__(256, 1) void gemm_tc(const float* __restrict__ bias) {
    extern __shared__ __nv_bfloat16 smem[];       // NSTAGE * STAGEB = 98304 bytes
    const int tid  = threadIdx.x;
    const int lane = tid & 31, wid = tid >> 5;
    const int wm = wid >> 2, wn = wid & 3;        // 2(m) x 4(n) warps; warp tile 64x32
    const int bm = blockIdx.y * GBM, bn = blockIdx.x * GBN;
    const int g = lane >> 2, tg = lane & 3;

    const uint32_t sbase = (uint32_t)__cvta_generic_to_shared(smem);

    float c[4][4][4];
#pragma unroll
    for (int mi = 0; mi < 4; mi++)
#pragma unroll
        for (int ni = 0; ni < 4; ni++)
#pragma unroll
            for (int k = 0; k < 4; k++) c[mi][ni][k] = 0.f;

    const int lr = tid >> 1, lc = tid & 1;
    const size_t offA = (size_t)(bm + lr) * SEQ + lc * 8;
    const size_t offB = (size_t)(bn + lr) * SEQ + lc * 8;
    const uint32_t ldst = (uint32_t)(lr * SROW + lc * 8) * 2;

    auto load_stage = [&](int st, int k0) {
        uint32_t d = sbase + st * STAGEB + ldst;
        CPASYNC16(d + 0 * MATB, g_xhi + offA + k0);
        CPASYNC16(d + 1 * MATB, g_xlo + offA + k0);
        CPASYNC16(d + 2 * MATB, g_whi + offB + k0);
        CPASYNC16(d + 3 * MATB, g_wlo + offB + k0);
        asm volatile("cp.async.commit_group;");
    };

    const int rA   = (lane & 7) + ((lane >> 3) & 1) * 8;
    const int colo = (lane >> 4) * 16;

    load_stage(0, 0);
    load_stage(1, GBK);
    load_stage(2, 2 * GBK);

    const int NIT = SEQ / GBK;                    // 32
    for (int it = 0; it < NIT; it++) {
        asm volatile("cp.async.wait_group 2;");
        __syncthreads();
        int nxt = it + 3;
        if (nxt < NIT) load_stage(nxt & 3, nxt * GBK);
        else           asm volatile("cp.async.commit_group;");

        const uint32_t st = sbase + (it & 3) * STAGEB;
        unsigned ah[4][4], al[4][4], bh[4][2], bl[4][2];
#pragma unroll
        for (int mi = 0; mi < 4; mi++) {
            uint32_t ad = st + (uint32_t)((wm * 64 + mi * 16 + rA) * SROW) * 2 + colo;
            LDM4(ah[mi], ad);
            LDM4(al[mi], ad + MATB);
        }
#pragma unroll
        for (int nj = 0; nj < 2; nj++) {
            uint32_t bd = st + 2 * MATB + (uint32_t)((wn * 32 + nj * 16 + rA) * SROW) * 2 + colo;
            unsigned r[4];
            LDM4(r, bd);
            bh[2 * nj][0] = r[0]; bh[2 * nj + 1][0] = r[1];
            bh[2 * nj][1] = r[2]; bh[2 * nj + 1][1] = r[3];
            LDM4(r, bd + MATB);
            bl[2 * nj][0] = r[0]; bl[2 * nj + 1][0] = r[1];
            bl[2 * nj][1] = r[2]; bl[2 * nj + 1][1] = r[3];
        }
#pragma unroll
        for (int mi = 0; mi < 4; mi++)
#pragma unroll
            for (int ni = 0; ni < 4; ni++) {
                MMA_BF16(c[mi][ni], ah[mi], bh[ni]);
                MMA_BF16(c[mi][ni], ah[mi], bl[ni]);
                MMA_BF16(c[mi][ni], al[mi], bh[ni]);
            }
    }

#pragma unroll
    for (int mi = 0; mi < 4; mi++) {
        int r0 = bm + wm * 64 + mi * 16 + g;
#pragma unroll
        for (int ni = 0; ni < 4; ni++) {
            int cc = bn + wn * 32 + ni * 8 + 2 * tg;
            float b0 = bias[cc] + 1e-6f;
            float b1 = bias[cc + 1] + 1e-6f;
            g_h[(size_t)r0 * DIM + cc]           = c[mi][ni][0] + b0;
            g_h[(size_t)r0 * DIM + cc + 1]       = c[mi][ni][1] + b1;
            g_h[(size_t)(r0 + 8) * DIM + cc]     = c[mi][ni][2] + b0;
            g_h[(size_t)(r0 + 8) * DIM + cc + 1] = c[mi][ni][3] + b1;
        }
    }
}

// ---------------- kernel 3: circuit with bit-regrouping ----------------
__device__ __forceinline__ int PHYS(int j) { return j ^ ((((j) >> 6) & 3) << 3); }

template <int DM>
__device__ __forceinline__ void local_gate(const float2* __restrict__ u,
                                           float* __restrict__ ar, float* __restrict__ ai) {
    const float2 u00 = u[0], u01 = u[1], u10 = u[2], u11 = u[3];
#pragma unroll
    for (int a = 0; a < 8; a++) {
        if (!(a & DM)) {
            float lr = ar[a], li = ai[a];
            float hr = ar[a + DM], hi2 = ai[a + DM];
            ar[a]      = u00.x * lr - u00.y * li + u01.x * hr - u01.y * hi2;
            ai[a]      = u00.x * li + u00.y * lr + u01.x * hi2 + u01.y * hr;
            ar[a + DM] = u10.x * lr - u10.y * li + u11.x * hr - u11.y * hi2;
            ai[a + DM] = u10.x * li + u10.y * lr + u11.x * hi2 + u11.y * hr;
        }
    }
}

__global__ __launch_bounds__(128, 8) void circuit_kernel(const float* __restrict__ Wout,
                                                         const float* __restrict__ bout,
                                                         float* __restrict__ out) {
    __shared__ float2 stage[2][DIM];              // ping-pong regroup buffers (16 KB)
    __shared__ float2 sg[NL * NQ * 4];
    __shared__ float  red[4][9];
    __shared__ float  sevn[NQ];

    const int t    = threadIdx.x;
    const int lane = t & 31;
    const int b    = blockIdx.x;

    // M0: amp j = 8t + a  (local bits 0-2)
    const float* hrow = g_h + (size_t)b * DIM + 8 * t;
    float4 hA = *(const float4*)hrow;
    float4 hB = *(const float4*)(hrow + 4);
    float ar[8] = {hA.x, hA.y, hA.z, hA.w, hB.x, hB.y, hB.z, hB.w};
    float ai[8] = {0.f, 0.f, 0.f, 0.f, 0.f, 0.f, 0.f, 0.f};

    for (int i = t; i < NL * NQ * 4; i += 128) sg[i] = g_gates[i];
    __syncthreads();

    // addressing bases
    const int m1base = ((t >> 3) << 6) | (t & 7);                        // M1: j = m1base | a<<3
    const int m2base = (((t >> 3) & 1) << 6) | (((t >> 6) & 1) << 5) |
                       (((t >> 5) & 1) << 4) | (((t >> 4) & 1) << 3) | (t & 7);  // M2: j = a<<7 | m2base
    const int pb0 = (8 * t) ^ ((((t >> 3) & 3)) << 3);                   // swizzled M0 base (contiguous)

    int buf = 0;
    for (int l = 0; l < NL; l++) {
        const float2* gl = sg + l * NQ * 4;

        // ---- G1 (M0): wires 9,8,7 act on local bits 0,1,2 ----
        local_gate<1>(gl + 4 * 9, ar, ai);
        local_gate<2>(gl + 4 * 8, ar, ai);
        local_gate<4>(gl + 4 * 7, ar, ai);

        // ---- R1: M0 -> M1 ----
        {
            float4* p = (float4*)&stage[buf][pb0];
            p[0] = make_float4(ar[0], ai[0], ar[1], ai[1]);
            p[1] = make_float4(ar[2], ai[2], ar[3], ai[3]);
            p[2] = make_float4(ar[4], ai[4], ar[5], ai[5]);
            p[3] = make_float4(ar[6], ai[6], ar[7], ai[7]);
        }
        __syncthreads();
#pragma unroll
        for (int a = 0; a < 8; a++) {
            float2 v = stage[buf][PHYS(m1base | (a << 3))];
            ar[a] = v.x; ai[a] = v.y;
        }

        // ---- G2 (M1): wires 6,5,4 act on global bits 3,4,5 (local 0,1,2) ----
        local_gate<1>(gl + 4 * 6, ar, ai);
        local_gate<2>(gl + 4 * 5, ar, ai);
        local_gate<4>(gl + 4 * 4, ar, ai);

        // ---- R2: M1 -> M2 (write other buffer) ----
#pragma unroll
        for (int a = 0; a < 8; a++)
            stage[buf ^ 1][PHYS(m1base | (a << 3))] = make_float2(ar[a], ai[a]);
        __syncthreads();
#pragma unroll
        for (int a = 0; a < 8; a++) {
            float2 v = stage[buf ^ 1][PHYS((a << 7) | m2base)];
            ar[a] = v.x; ai[a] = v.y;
        }

        // ---- G3 (M2): wires 2,1,0 act on global bits 7,8,9 (local 0,1,2) ----
        local_gate<1>(gl + 4 * 2, ar, ai);
        local_gate<2>(gl + 4 * 1, ar, ai);
        local_gate<4>(gl + 4 * 0, ar, ai);

        // ---- shfl gate: wire 3 on global bit 6 = lane bit 3 ----
        {
            const float2 u00 = gl[12], u01 = gl[13], u10 = gl[14], u11 = gl[15];
            const bool hib = (t >> 3) & 1;
            const float2 va = hib ? u11 : u00;
            const float2 vb = hib ? u10 : u01;
#pragma unroll
            for (int a = 0; a < 8; a++) {
                float pr = __shfl_xor_sync(0xffffffffu, ar[a], 8);
                float pi = __shfl_xor_sync(0xffffffffu, ai[a], 8);
                float nr = va.x * ar[a] - va.y * ai[a] + vb.x * pr - vb.y * pi;
                float ni = va.x * ai[a] + va.y * ar[a] + vb.x * pi + vb.y * pr;
                ar[a] = nr; ai[a] = ni;
            }
        }

        // ---- R3: M2 -> M0 fused with layer permutation ----
#pragma unroll
        for (int a = 0; a < 8; a++)
            stage[buf][PHYS((a << 7) | m2base)] = make_float2(ar[a], ai[a]);
        __syncthreads();
        {
            const int* pm = g_perm + l * DIM + 8 * t;
            int4 pa = *(const int4*)pm;
            int4 pb4 = *(const int4*)(pm + 4);
            int pp[8] = {pa.x, pa.y, pa.z, pa.w, pb4.x, pb4.y, pb4.z, pb4.w};
#pragma unroll
            for (int a = 0; a < 8; a++) {
                float2 v = stage[buf][PHYS(pp[a])];
                ar[a] = v.x; ai[a] = v.y;
            }
        }
        buf ^= 1;
    }

    // ---- expvals (unnormalized; normalized by total prob) ----
    float p[8];
#pragma unroll
    for (int a = 0; a < 8; a++) p[a] = ar[a] * ar[a] + ai[a] * ai[a];
    float ps = ((p[0] + p[1]) + (p[2] + p[3])) + ((p[4] + p[5]) + (p[6] + p[7]));

    float v[9];
    v[0] = ps;
#pragma unroll
    for (int i = 0; i < 5; i++)                              // q = 2+i, lane bit 4-i
        v[1 + i] = ((lane >> (4 - i)) & 1) ? -ps : ps;
    v[6] = ((p[0] + p[1]) + (p[2] + p[3])) - ((p[4] + p[5]) + (p[6] + p[7]));  // q7
    v[7] = ((p[0] + p[1]) + (p[4] + p[5])) - ((p[2] + p[3]) + (p[6] + p[7]));  // q8
    v[8] = ((p[0] + p[2]) + (p[4] + p[6])) - ((p[1] + p[3]) + (p[5] + p[7]));  // q9

#pragma unroll
    for (int j = 0; j < 9; j++) {
#pragma unroll
        for (int o = 16; o; o >>= 1) v[j] += __shfl_xor_sync(0xffffffffu, v[j], o);
    }
    if (lane == 0) {
        int wi = t >> 5;
#pragma unroll
        for (int j = 0; j < 9; j++) red[wi][j] = v[j];
    }
    __syncthreads();

    if (t < NQ) {
        const int q = t;
        float pst = ((red[0][0] + red[1][0]) + (red[2][0] + red[3][0]));
        float e;
        if (q >= 2) {
            e = ((red[0][q - 1] + red[1][q - 1]) + (red[2][q - 1] + red[3][q - 1]));
        } else if (q == 0) {   // j bit9 = warp bit1
            e = (red[0][0] + red[1][0]) - (red[2][0] + red[3][0]);
        } else {               // j bit8 = warp bit0
            e = (red[0][0] - red[1][0]) + (red[2][0] - red[3][0]);
        }
        sevn[q] = e / pst;
    }
    __syncthreads();

    if (t < PRED) {
        float o = bout[t];
#pragma unroll
        for (int q = 0; q < NQ; q++) o += sevn[q] * Wout[t * NQ + q];
        out[(size_t)b * PRED + t] = o;
    }
}

// ---------------- launch ----------------
extern "C" void kernel_launch(void* const* d_in, const int* in_sizes, int n_in,
                              void* d_out, int out_size) {
    const float* x     = (const float*)d_in[0];
    const float* W_in  = (const float*)d_in[1];
    const float* b_in  = (const float*)d_in[2];
    const float* qw    = (const float*)d_in[3];
    const float* W_out = (const float*)d_in[4];
    const float* b_out = (const float*)d_in[5];
    float* out = (float*)d_out;

    cudaFuncSetAttribute(gemm_tc, cudaFuncAttributeMaxDynamicSharedMemorySize,
                         NSTAGE * STAGEB);

    split_kernel<<<(BATCH * SEQ + 255) / 256, 256>>>(x, W_in, qw);
    dim3 grid(DIM / GBN, BATCH / GBM);
    gemm_tc<<<grid, 256, NSTAGE * STAGEB>>>(b_in);
    circuit_kernel<<<BATCH, 128>>>(W_out, b_out, out);
}